// round 3
// baseline (speedup 1.0000x reference)
#include <cuda_runtime.h>
#include <cuda_bf16.h>

#define NN   50000
#define EE   800000
#define DH   128

// ---------------- device scratch (static globals: no allocation) ----------
__device__ int   g_is64;
__device__ int   g_src[EE];
__device__ int   g_dst[EE];
__device__ int   g_cnt[NN];     // in-degree (excluding self loop)
__device__ int   g_off[NN];     // CSR offsets (exclusive scan of cnt)
__device__ int   g_pos[NN];     // scatter cursors
__device__ float g_dinv[NN];    // 1/sqrt(deg) with self-loop
__device__ int   g_ssrc[EE];    // CSR-sorted edge sources
__device__ float g_snorm[EE];   // CSR-sorted edge norms
__device__ float g_xw[NN * DH]; // GEMM output buffer
__device__ float g_h [NN * DH]; // layer feature buffer

// ---------------- dtype detection (int64 vs int32 edge_index) -------------
__global__ void k_detect(const void* ei) {
    const unsigned* p = (const unsigned*)ei;
    int is64 = 1;
    for (int i = 0; i < 64; i++) {
        if (p[2 * i + 1] != 0u) { is64 = 0; break; }
    }
    g_is64 = is64;
}

__global__ void k_convert(const void* ei) {
    int e = blockIdx.x * blockDim.x + threadIdx.x;
    if (e >= EE) return;
    if (g_is64) {
        const long long* p = (const long long*)ei;
        g_src[e] = (int)p[e];
        g_dst[e] = (int)p[EE + e];
    } else {
        const int* p = (const int*)ei;
        g_src[e] = p[e];
        g_dst[e] = p[EE + e];
    }
}

// ---------------- degree / norm / CSR build -------------------------------
__global__ void k_zero() {
    int i = blockIdx.x * blockDim.x + threadIdx.x;
    if (i < NN) { g_cnt[i] = 0; g_pos[i] = 0; }
}

__global__ void k_count() {
    int e = blockIdx.x * blockDim.x + threadIdx.x;
    if (e >= EE) return;
    atomicAdd(&g_cnt[g_dst[e]], 1);
}

__global__ void k_dinv() {
    int i = blockIdx.x * blockDim.x + threadIdx.x;
    if (i < NN) g_dinv[i] = rsqrtf((float)g_cnt[i] + 1.0f);  // +1 self loop
}

// single-block exclusive scan of g_cnt -> g_off
__global__ void k_scan() {
    __shared__ int sh[1024];
    __shared__ int carry;
    if (threadIdx.x == 0) carry = 0;
    __syncthreads();
    for (int base = 0; base < NN; base += 1024) {
        int i = base + (int)threadIdx.x;
        int v = (i < NN) ? g_cnt[i] : 0;
        sh[threadIdx.x] = v;
        __syncthreads();
        #pragma unroll
        for (int d = 1; d < 1024; d <<= 1) {
            int t = (threadIdx.x >= (unsigned)d) ? sh[threadIdx.x - d] : 0;
            __syncthreads();
            sh[threadIdx.x] += t;
            __syncthreads();
        }
        int incl = sh[threadIdx.x];
        if (i < NN) g_off[i] = carry + incl - v;  // exclusive
        __syncthreads();
        if (threadIdx.x == 0) carry += sh[1023];
        __syncthreads();
    }
}

__global__ void k_scatter() {
    int e = blockIdx.x * blockDim.x + threadIdx.x;
    if (e >= EE) return;
    int s = g_src[e];
    int d = g_dst[e];
    int p = g_off[d] + atomicAdd(&g_pos[d], 1);
    g_ssrc[p]  = s;
    g_snorm[p] = g_dinv[s] * g_dinv[d];
}

// ---------------- GEMM: g_xw = A[N,128] @ W[128,128] ----------------------
// 128x128 block tile, 256 threads, 8x8 register tile per thread.
// A == nullptr means "read from g_h" (device-side symbol — valid in device code).
__global__ __launch_bounds__(256) void k_gemm(const float* __restrict__ A_in,
                                              const float* __restrict__ W) {
    const float* A = A_in ? A_in : (const float*)g_h;

    __shared__ float As[128][36];   // padded, k-chunk of 32
    __shared__ float Ws[32][128];

    int tx = threadIdx.x & 15;   // col group
    int ty = threadIdx.x >> 4;   // row group
    int r0 = blockIdx.x * 128;

    float acc[8][8];
    #pragma unroll
    for (int i = 0; i < 8; i++)
        #pragma unroll
        for (int j = 0; j < 8; j++) acc[i][j] = 0.0f;

    for (int k0 = 0; k0 < DH; k0 += 32) {
        // load A tile: 128 rows x 32 cols (float4 per thread x4)
        #pragma unroll
        for (int q = threadIdx.x; q < 1024; q += 256) {
            int r  = q >> 3;
            int kq = (q & 7) * 4;
            float4 v = make_float4(0.f, 0.f, 0.f, 0.f);
            int row = r0 + r;
            if (row < NN) v = *(const float4*)&A[row * DH + k0 + kq];
            *(float4*)&As[r][kq] = v;
        }
        // load W tile: 32 rows x 128 cols
        #pragma unroll
        for (int q = threadIdx.x; q < 1024; q += 256) {
            int kk = q >> 5;
            int c  = (q & 31) * 4;
            *(float4*)&Ws[kk][c] = *(const float4*)&W[(k0 + kk) * DH + c];
        }
        __syncthreads();

        #pragma unroll
        for (int kk = 0; kk < 32; kk++) {
            float a[8], w[8];
            #pragma unroll
            for (int i = 0; i < 8; i++) a[i] = As[ty + 16 * i][kk];
            #pragma unroll
            for (int j = 0; j < 8; j++) w[j] = Ws[kk][tx + 16 * j];
            #pragma unroll
            for (int i = 0; i < 8; i++)
                #pragma unroll
                for (int j = 0; j < 8; j++)
                    acc[i][j] = fmaf(a[i], w[j], acc[i][j]);
        }
        __syncthreads();
    }

    #pragma unroll
    for (int i = 0; i < 8; i++) {
        int row = r0 + ty + 16 * i;
        if (row < NN) {
            #pragma unroll
            for (int j = 0; j < 8; j++)
                g_xw[row * DH + tx + 16 * j] = acc[i][j];
        }
    }
}

// ---------------- aggregation: g_h = relu( Ahat @ g_xw + b ) --------------
// one warp per node; lane handles one float4 (32*16B = 512B row)
__global__ __launch_bounds__(256) void k_agg(const float* __restrict__ b) {
    int warp = (blockIdx.x * blockDim.x + threadIdx.x) >> 5;
    int lane = threadIdx.x & 31;
    if (warp >= NN) return;
    int node = warp;

    const float4* xw4 = (const float4*)g_xw;

    float dv   = g_dinv[node];
    float self = dv * dv;
    float4 s   = xw4[node * 32 + lane];
    float4 acc = make_float4(s.x * self, s.y * self, s.z * self, s.w * self);

    int start = g_off[node];
    int m     = g_cnt[node];

    int j = 0;
    for (; j + 1 < m; j += 2) {
        int   s0 = g_ssrc[start + j];
        int   s1 = g_ssrc[start + j + 1];
        float n0 = g_snorm[start + j];
        float n1 = g_snorm[start + j + 1];
        float4 v0 = xw4[s0 * 32 + lane];
        float4 v1 = xw4[s1 * 32 + lane];
        acc.x += v0.x * n0 + v1.x * n1;
        acc.y += v0.y * n0 + v1.y * n1;
        acc.z += v0.z * n0 + v1.z * n1;
        acc.w += v0.w * n0 + v1.w * n1;
    }
    if (j < m) {
        int   s0 = g_ssrc[start + j];
        float n0 = g_snorm[start + j];
        float4 v0 = xw4[s0 * 32 + lane];
        acc.x += v0.x * n0;
        acc.y += v0.y * n0;
        acc.z += v0.z * n0;
        acc.w += v0.w * n0;
    }

    float4 bb = ((const float4*)b)[lane];
    acc.x = fmaxf(acc.x + bb.x, 0.0f);
    acc.y = fmaxf(acc.y + bb.y, 0.0f);
    acc.z = fmaxf(acc.z + bb.z, 0.0f);
    acc.w = fmaxf(acc.w + bb.w, 0.0f);

    ((float4*)g_h)[node * 32 + lane] = acc;
}

// ---------------- final FC: out[n] = dot(h[n], Wfc) + bfc -----------------
__global__ __launch_bounds__(256) void k_fc(const float* __restrict__ Wfc,
                                            const float* __restrict__ bfc,
                                            float* __restrict__ out) {
    int warp = (blockIdx.x * blockDim.x + threadIdx.x) >> 5;
    int lane = threadIdx.x & 31;
    if (warp >= NN) return;

    float4 h = ((const float4*)g_h)[warp * 32 + lane];
    float4 w = ((const float4*)Wfc)[lane];
    float sum = h.x * w.x + h.y * w.y + h.z * w.z + h.w * w.w;
    #pragma unroll
    for (int d = 16; d > 0; d >>= 1)
        sum += __shfl_xor_sync(0xFFFFFFFFu, sum, d);
    if (lane == 0) out[warp] = sum + bfc[0];
}

// ---------------- launch ---------------------------------------------------
extern "C" void kernel_launch(void* const* d_in, const int* in_sizes, int n_in,
                              void* d_out, int out_size) {
    const float* x    = (const float*)d_in[0];
    const void*  ei   = d_in[1];
    const float* W1   = (const float*)d_in[2];
    const float* b1   = (const float*)d_in[3];
    const float* W2   = (const float*)d_in[4];
    const float* b2   = (const float*)d_in[5];
    const float* W3   = (const float*)d_in[6];
    const float* b3   = (const float*)d_in[7];
    const float* Wfc  = (const float*)d_in[8];
    const float* bfc  = (const float*)d_in[9];
    float* out = (float*)d_out;

    const int TB = 256;
    int ge = (EE + TB - 1) / TB;
    int gn = (NN + TB - 1) / TB;

    k_detect<<<1, 1>>>(ei);
    k_convert<<<ge, TB>>>(ei);
    k_zero<<<gn, TB>>>();
    k_count<<<ge, TB>>>();
    k_dinv<<<gn, TB>>>();
    k_scan<<<1, 1024>>>();
    k_scatter<<<ge, TB>>>();

    int ggemm = (NN + 127) / 128;
    int gwarp = (NN * 32 + TB - 1) / TB;  // one warp per node

    // layer 1 (A = x from harness)
    k_gemm<<<ggemm, TB>>>(x, W1);
    k_agg<<<gwarp, TB>>>(b1);
    // layer 2 (A = g_h, resolved inside the kernel)
    k_gemm<<<ggemm, TB>>>(nullptr, W2);
    k_agg<<<gwarp, TB>>>(b2);
    // layer 3
    k_gemm<<<ggemm, TB>>>(nullptr, W3);
    k_agg<<<gwarp, TB>>>(b3);
    // head
    k_fc<<<gwarp, TB>>>(Wfc, bfc, out);
}

// round 7
// speedup vs baseline: 1.3125x; 1.3125x over previous
#include <cuda_runtime.h>
#include <cuda_bf16.h>
#include <cstdint>

#define NN   50000
#define EE   800000
#define DH   128

// ---------------- device scratch ----------
__device__ int   g_is64;
__device__ int   g_src[EE];
__device__ int   g_dst[EE];
__device__ int   g_cnt[NN];
__device__ int   g_off[NN];
__device__ int   g_pos[NN];
__device__ float g_dinv[NN];
__device__ int   g_ssrc[EE];
__device__ float g_snorm[EE];
__device__ float g_xw[NN * DH];
__device__ float g_h [NN * DH];
__device__ unsigned short g_wtbh[DH * DH];  // W^T hi, bf16 bits, [n][k]
__device__ unsigned short g_wtbl[DH * DH];  // W^T lo, bf16 bits, [n][k]

// ---------------- dtype detection ----------------
__global__ void k_detect(const void* ei) {
    const unsigned* p = (const unsigned*)ei;
    int is64 = 1;
    for (int i = 0; i < 64; i++)
        if (p[2 * i + 1] != 0u) { is64 = 0; break; }
    g_is64 = is64;
}

__global__ void k_zero() {
    int i = blockIdx.x * blockDim.x + threadIdx.x;
    if (i < NN) { g_cnt[i] = 0; g_pos[i] = 0; }
}

__global__ void k_convert_count(const void* ei) {
    int e = blockIdx.x * blockDim.x + threadIdx.x;
    if (e >= EE) return;
    int s, d;
    if (g_is64) {
        const long long* p = (const long long*)ei;
        s = (int)p[e]; d = (int)p[EE + e];
    } else {
        const int* p = (const int*)ei;
        s = p[e]; d = p[EE + e];
    }
    g_src[e] = s; g_dst[e] = d;
    atomicAdd(&g_cnt[d], 1);
}

__global__ void k_dinv() {
    int i = blockIdx.x * blockDim.x + threadIdx.x;
    if (i < NN) g_dinv[i] = rsqrtf((float)g_cnt[i] + 1.0f);
}

// single-block exclusive scan, shfl-based
__global__ void k_scan() {
    __shared__ int wsum[32];
    const int C = (NN + 1023) / 1024;
    int t = threadIdx.x, lane = t & 31, wid = t >> 5;
    int beg = t * C;
    int end = min(beg + C, NN);
    int s = 0;
    for (int i = beg; i < end; i++) s += g_cnt[i];
    int v = s;
    #pragma unroll
    for (int d = 1; d < 32; d <<= 1) {
        int u = __shfl_up_sync(0xFFFFFFFFu, v, d);
        if (lane >= d) v += u;
    }
    if (lane == 31) wsum[wid] = v;
    __syncthreads();
    if (wid == 0) {
        int w = wsum[lane];
        #pragma unroll
        for (int d = 1; d < 32; d <<= 1) {
            int u = __shfl_up_sync(0xFFFFFFFFu, w, d);
            if (lane >= d) w += u;
        }
        wsum[lane] = w;
    }
    __syncthreads();
    int run = v - s + (wid ? wsum[wid - 1] : 0);
    for (int i = beg; i < end; i++) {
        int c = g_cnt[i];
        g_off[i] = run;
        run += c;
    }
}

__global__ void k_scatter() {
    int e = blockIdx.x * blockDim.x + threadIdx.x;
    if (e >= EE) return;
    int s = g_src[e];
    int d = g_dst[e];
    int p = g_off[d] + atomicAdd(&g_pos[d], 1);
    g_ssrc[p]  = s;
    g_snorm[p] = g_dinv[s] * g_dinv[d];
}

// ---------------- W prep: transpose + bf16 hi/lo split ----------------
__global__ void k_wprep(const float* __restrict__ W) {
    int n = blockIdx.x, k = threadIdx.x;
    float v = W[k * DH + n];
    __nv_bfloat16 hb = __float2bfloat16_rn(v);
    float hf = __bfloat162float(hb);
    __nv_bfloat16 lb = __float2bfloat16_rn(v - hf);
    g_wtbh[n * DH + k] = __bfloat16_as_ushort(hb);
    g_wtbl[n * DH + k] = __bfloat16_as_ushort(lb);
}

// ---------------- bf16x3 mma GEMM: g_xw = A @ W ------------------------
// CTA tile 128x128, K=128 resident. 256 threads = 8 warps (2x4 warp grid,
// warp tile 64x32). Rows padded to 272B for conflict-free fragment LDS.
#define ROWB 272
#define SM_AH 0
#define SM_AL (SM_AH + 128 * ROWB)
#define SM_BH (SM_AL + 128 * ROWB)
#define SM_BL (SM_BH + 128 * ROWB)
#define SM_GEMM_TOTAL (SM_BL + 128 * ROWB)   // 139264 B

__device__ __forceinline__ void mma_bf16(float* d, uint32_t a0, uint32_t a1,
                                         uint32_t a2, uint32_t a3,
                                         uint32_t b0, uint32_t b1) {
    asm volatile(
        "mma.sync.aligned.m16n8k16.row.col.f32.bf16.bf16.f32 "
        "{%0,%1,%2,%3}, {%4,%5,%6,%7}, {%8,%9}, {%0,%1,%2,%3};"
        : "+f"(d[0]), "+f"(d[1]), "+f"(d[2]), "+f"(d[3])
        : "r"(a0), "r"(a1), "r"(a2), "r"(a3), "r"(b0), "r"(b1));
}

__global__ __launch_bounds__(256) void k_gemm_mma(const float* __restrict__ A_in) {
    const float* A = A_in ? A_in : (const float*)g_h;
    extern __shared__ char sm[];
    int tid  = threadIdx.x;
    int wid  = tid >> 5;
    int lane = tid & 31;
    int r0   = blockIdx.x * 128;

    // ---- load A: fp32 -> bf16 hi/lo, row-major [128][128] padded ----
    {
        int r  = tid >> 1;
        int c0 = (tid & 1) * 64;
        bool valid = (r0 + r) < NN;
        const float4* src = (const float4*)(A + (size_t)(r0 + r) * DH + c0);
        char* dh = sm + SM_AH + r * ROWB + c0 * 2;
        char* dl = sm + SM_AL + r * ROWB + c0 * 2;
        #pragma unroll
        for (int i = 0; i < 16; i++) {
            float4 v = valid ? src[i] : make_float4(0.f, 0.f, 0.f, 0.f);
            __nv_bfloat16 hx = __float2bfloat16_rn(v.x);
            __nv_bfloat16 hy = __float2bfloat16_rn(v.y);
            __nv_bfloat16 hz = __float2bfloat16_rn(v.z);
            __nv_bfloat16 hw = __float2bfloat16_rn(v.w);
            uint32_t h01 = (uint32_t)__bfloat16_as_ushort(hx)
                         | ((uint32_t)__bfloat16_as_ushort(hy) << 16);
            uint32_t h23 = (uint32_t)__bfloat16_as_ushort(hz)
                         | ((uint32_t)__bfloat16_as_ushort(hw) << 16);
            __nv_bfloat16 lx = __float2bfloat16_rn(v.x - __bfloat162float(hx));
            __nv_bfloat16 ly = __float2bfloat16_rn(v.y - __bfloat162float(hy));
            __nv_bfloat16 lz = __float2bfloat16_rn(v.z - __bfloat162float(hz));
            __nv_bfloat16 lw = __float2bfloat16_rn(v.w - __bfloat162float(hw));
            uint32_t l01 = (uint32_t)__bfloat16_as_ushort(lx)
                         | ((uint32_t)__bfloat16_as_ushort(ly) << 16);
            uint32_t l23 = (uint32_t)__bfloat16_as_ushort(lz)
                         | ((uint32_t)__bfloat16_as_ushort(lw) << 16);
            *(uint2*)(dh + i * 8) = make_uint2(h01, h23);
            *(uint2*)(dl + i * 8) = make_uint2(l01, l23);
        }
    }
    // ---- load B: pre-split W^T bf16 [n][k] -> padded SMEM ----
    {
        int n  = tid >> 1;
        int c0 = (tid & 1) * 64;
        const uint4* sh = (const uint4*)(g_wtbh + n * DH + c0);
        const uint4* sl = (const uint4*)(g_wtbl + n * DH + c0);
        uint4* dh = (uint4*)(sm + SM_BH + n * ROWB + c0 * 2);
        uint4* dl = (uint4*)(sm + SM_BL + n * ROWB + c0 * 2);
        #pragma unroll
        for (int i = 0; i < 8; i++) { dh[i] = sh[i]; dl[i] = sl[i]; }
    }
    __syncthreads();

    // warp grid: wm = wid & 1 (2 x 64 rows), wn = wid >> 1 (4 x 32 cols)
    int wm = (wid & 1) * 64;
    int wn = (wid >> 1) * 32;
    int g  = lane >> 2;      // 0..7
    int t  = lane & 3;       // 0..3

    float acc[4][4][4];      // [mt][nt][4]
    #pragma unroll
    for (int mt = 0; mt < 4; mt++)
        #pragma unroll
        for (int nt = 0; nt < 4; nt++)
            #pragma unroll
            for (int q = 0; q < 4; q++) acc[mt][nt][q] = 0.0f;

    #pragma unroll
    for (int ks = 0; ks < 8; ks++) {
        int kb = ks * 32;    // byte offset of k-chunk (16 elems * 2B)
        uint32_t bh[4][2], bl[4][2];
        #pragma unroll
        for (int nt = 0; nt < 4; nt++) {
            int nrow = wn + nt * 8 + g;
            const char* ph = sm + SM_BH + nrow * ROWB + kb + t * 4;
            const char* pl = sm + SM_BL + nrow * ROWB + kb + t * 4;
            bh[nt][0] = *(const uint32_t*)(ph);
            bh[nt][1] = *(const uint32_t*)(ph + 16);
            bl[nt][0] = *(const uint32_t*)(pl);
            bl[nt][1] = *(const uint32_t*)(pl + 16);
        }
        #pragma unroll
        for (int mt = 0; mt < 4; mt++) {
            int mrow = wm + mt * 16 + g;
            const char* ph = sm + SM_AH + mrow * ROWB + kb + t * 4;
            const char* pl = sm + SM_AL + mrow * ROWB + kb + t * 4;
            uint32_t ah0 = *(const uint32_t*)(ph);
            uint32_t ah1 = *(const uint32_t*)(ph + 8 * ROWB);
            uint32_t ah2 = *(const uint32_t*)(ph + 16);
            uint32_t ah3 = *(const uint32_t*)(ph + 8 * ROWB + 16);
            uint32_t al0 = *(const uint32_t*)(pl);
            uint32_t al1 = *(const uint32_t*)(pl + 8 * ROWB);
            uint32_t al2 = *(const uint32_t*)(pl + 16);
            uint32_t al3 = *(const uint32_t*)(pl + 8 * ROWB + 16);
            #pragma unroll
            for (int nt = 0; nt < 4; nt++) {
                mma_bf16(acc[mt][nt], ah0, ah1, ah2, ah3, bh[nt][0], bh[nt][1]);
                mma_bf16(acc[mt][nt], ah0, ah1, ah2, ah3, bl[nt][0], bl[nt][1]);
                mma_bf16(acc[mt][nt], al0, al1, al2, al3, bh[nt][0], bh[nt][1]);
            }
        }
    }

    // ---- epilogue: write D to g_xw ----
    #pragma unroll
    for (int mt = 0; mt < 4; mt++) {
        int row = r0 + wm + mt * 16 + g;
        #pragma unroll
        for (int nt = 0; nt < 4; nt++) {
            int col = wn + nt * 8 + t * 2;
            if (row < NN)
                *(float2*)(g_xw + (size_t)row * DH + col) =
                    make_float2(acc[mt][nt][0], acc[mt][nt][1]);
            if (row + 8 < NN)
                *(float2*)(g_xw + (size_t)(row + 8) * DH + col) =
                    make_float2(acc[mt][nt][2], acc[mt][nt][3]);
        }
    }
}

// ---------------- aggregation: g_h = relu( Ahat @ g_xw + b ) ------------
// last layer: fuse FC head (dot with Wfc, + bfc) directly to out.
__global__ __launch_bounds__(256) void k_agg(const float* __restrict__ b,
                                             const float* __restrict__ Wfc,
                                             const float* __restrict__ bfc,
                                             float* __restrict__ out) {
    int warp = (blockIdx.x * blockDim.x + threadIdx.x) >> 5;
    int lane = threadIdx.x & 31;
    if (warp >= NN) return;
    int node = warp;

    const float4* xw4 = (const float4*)g_xw;

    float dv   = g_dinv[node];
    float self = dv * dv;
    float4 s   = xw4[node * 32 + lane];
    float4 acc = make_float4(s.x * self, s.y * self, s.z * self, s.w * self);

    int start = g_off[node];
    int m     = g_cnt[node];

    int j = 0;
    for (; j + 1 < m; j += 2) {
        int   s0 = g_ssrc[start + j];
        int   s1 = g_ssrc[start + j + 1];
        float n0 = g_snorm[start + j];
        float n1 = g_snorm[start + j + 1];
        float4 v0 = xw4[s0 * 32 + lane];
        float4 v1 = xw4[s1 * 32 + lane];
        acc.x += v0.x * n0 + v1.x * n1;
        acc.y += v0.y * n0 + v1.y * n1;
        acc.z += v0.z * n0 + v1.z * n1;
        acc.w += v0.w * n0 + v1.w * n1;
    }
    if (j < m) {
        int   s0 = g_ssrc[start + j];
        float n0 = g_snorm[start + j];
        float4 v0 = xw4[s0 * 32 + lane];
        acc.x += v0.x * n0;
        acc.y += v0.y * n0;
        acc.z += v0.z * n0;
        acc.w += v0.w * n0;
    }

    float4 bb = ((const float4*)b)[lane];
    acc.x = fmaxf(acc.x + bb.x, 0.0f);
    acc.y = fmaxf(acc.y + bb.y, 0.0f);
    acc.z = fmaxf(acc.z + bb.z, 0.0f);
    acc.w = fmaxf(acc.w + bb.w, 0.0f);

    if (Wfc) {
        float4 w = ((const float4*)Wfc)[lane];
        float sum = acc.x * w.x + acc.y * w.y + acc.z * w.z + acc.w * w.w;
        #pragma unroll
        for (int d = 16; d > 0; d >>= 1)
            sum += __shfl_xor_sync(0xFFFFFFFFu, sum, d);
        if (lane == 0) out[node] = sum + bfc[0];
    } else {
        ((float4*)g_h)[node * 32 + lane] = acc;
    }
}

// ---------------- launch -------------------------------------------------
extern "C" void kernel_launch(void* const* d_in, const int* in_sizes, int n_in,
                              void* d_out, int out_size) {
    const float* x    = (const float*)d_in[0];
    const void*  ei   = d_in[1];
    const float* W1   = (const float*)d_in[2];
    const float* b1   = (const float*)d_in[3];
    const float* W2   = (const float*)d_in[4];
    const float* b2   = (const float*)d_in[5];
    const float* W3   = (const float*)d_in[6];
    const float* b3   = (const float*)d_in[7];
    const float* Wfc  = (const float*)d_in[8];
    const float* bfc  = (const float*)d_in[9];
    float* out = (float*)d_out;

    static int smem_set = 0;
    if (!smem_set) {
        cudaFuncSetAttribute(k_gemm_mma,
                             cudaFuncAttributeMaxDynamicSharedMemorySize,
                             SM_GEMM_TOTAL);
        smem_set = 1;
    }

    const int TB = 256;
    int ge = (EE + TB - 1) / TB;
    int gn = (NN + TB - 1) / TB;

    k_detect<<<1, 1>>>(ei);
    k_zero<<<gn, TB>>>();
    k_convert_count<<<ge, TB>>>(ei);
    k_dinv<<<gn, TB>>>();
    k_scan<<<1, 1024>>>();
    k_scatter<<<ge, TB>>>();

    int ggemm = (NN + 127) / 128;
    int gwarp = (NN * 32 + TB - 1) / TB;

    // layer 1
    k_wprep<<<DH, DH>>>(W1);
    k_gemm_mma<<<ggemm, 256, SM_GEMM_TOTAL>>>(x);
    k_agg<<<gwarp, TB>>>(b1, nullptr, nullptr, nullptr);
    // layer 2
    k_wprep<<<DH, DH>>>(W2);
    k_gemm_mma<<<ggemm, 256, SM_GEMM_TOTAL>>>(nullptr);
    k_agg<<<gwarp, TB>>>(b2, nullptr, nullptr, nullptr);
    // layer 3 + fused FC head
    k_wprep<<<DH, DH>>>(W3);
    k_gemm_mma<<<ggemm, 256, SM_GEMM_TOTAL>>>(nullptr);
    k_agg<<<gwarp, TB>>>(b3, Wfc, bfc, out);
}

// round 11
// speedup vs baseline: 1.3469x; 1.0262x over previous
#include <cuda_runtime.h>
#include <cuda_bf16.h>
#include <cuda_fp16.h>
#include <cstdint>

#define NN   50000
#define EE   800000
#define DH   128

// ---------------- device scratch ----------
__device__ int    g_is64;
__device__ int    g_src[EE];
__device__ int    g_dst[EE];
__device__ int    g_cnt[NN];
__device__ int    g_off[NN];
__device__ int    g_pos[NN];
__device__ float  g_dinv[NN];
__device__ int    g_ssrc[EE];
__device__ float  g_snorm[EE];
__device__ __half g_xwh[NN * DH];   // GEMM output, fp16 (gather payload)
__device__ float  g_h [NN * DH];    // layer feature buffer (fp32)

// ---------------- zero + dtype detection (fused) ----------------
__global__ void k_dz(const void* ei) {
    int i = blockIdx.x * blockDim.x + threadIdx.x;
    if (i < NN) { g_cnt[i] = 0; g_pos[i] = 0; }
    if (i == 0) {
        const unsigned* p = (const unsigned*)ei;
        int is64 = 1;
        for (int q = 0; q < 64; q++)
            if (p[2 * q + 1] != 0u) { is64 = 0; break; }
        g_is64 = is64;
    }
}

__global__ void k_convert_count(const void* ei) {
    int e = blockIdx.x * blockDim.x + threadIdx.x;
    if (e >= EE) return;
    int s, d;
    if (g_is64) {
        const long long* p = (const long long*)ei;
        s = (int)p[e]; d = (int)p[EE + e];
    } else {
        const int* p = (const int*)ei;
        s = p[e]; d = p[EE + e];
    }
    g_src[e] = s; g_dst[e] = d;
    atomicAdd(&g_cnt[d], 1);
}

// single-block exclusive scan (shfl-based) + dinv (fused)
__global__ void k_scan() {
    __shared__ int wsum[32];
    const int C = (NN + 1023) / 1024;
    int t = threadIdx.x, lane = t & 31, wid = t >> 5;
    int beg = t * C;
    int end = min(beg + C, NN);
    int s = 0;
    for (int i = beg; i < end; i++) s += g_cnt[i];
    int v = s;
    #pragma unroll
    for (int d = 1; d < 32; d <<= 1) {
        int u = __shfl_up_sync(0xFFFFFFFFu, v, d);
        if (lane >= d) v += u;
    }
    if (lane == 31) wsum[wid] = v;
    __syncthreads();
    if (wid == 0) {
        int w = wsum[lane];
        #pragma unroll
        for (int d = 1; d < 32; d <<= 1) {
            int u = __shfl_up_sync(0xFFFFFFFFu, w, d);
            if (lane >= d) w += u;
        }
        wsum[lane] = w;
    }
    __syncthreads();
    int run = v - s + (wid ? wsum[wid - 1] : 0);
    for (int i = beg; i < end; i++) {
        int c = g_cnt[i];
        g_off[i] = run;
        g_dinv[i] = rsqrtf((float)c + 1.0f);
        run += c;
    }
}

__global__ void k_scatter() {
    int e = blockIdx.x * blockDim.x + threadIdx.x;
    if (e >= EE) return;
    int s = g_src[e];
    int d = g_dst[e];
    int p = g_off[d] + atomicAdd(&g_pos[d], 1);
    g_ssrc[p]  = s;
    g_snorm[p] = g_dinv[s] * g_dinv[d];
}

// ---------------- bf16x3 mma GEMM: g_xwh = fp16( A @ W ) ----------------
// CTA tile 128x128, K=128 resident. 256 threads = 8 warps (2x4 warp grid,
// warp tile 64x32). Rows padded to 272B for conflict-free fragment LDS.
// W is split to bf16 hi/lo + transposed inline (W stays L2-resident).
#define ROWB 272
#define SM_AH 0
#define SM_AL (SM_AH + 128 * ROWB)
#define SM_BH (SM_AL + 128 * ROWB)
#define SM_BL (SM_BH + 128 * ROWB)
#define SM_GEMM_TOTAL (SM_BL + 128 * ROWB)   // 139264 B

__device__ __forceinline__ void mma_bf16(float* d, uint32_t a0, uint32_t a1,
                                         uint32_t a2, uint32_t a3,
                                         uint32_t b0, uint32_t b1) {
    asm volatile(
        "mma.sync.aligned.m16n8k16.row.col.f32.bf16.bf16.f32 "
        "{%0,%1,%2,%3}, {%4,%5,%6,%7}, {%8,%9}, {%0,%1,%2,%3};"
        : "+f"(d[0]), "+f"(d[1]), "+f"(d[2]), "+f"(d[3])
        : "r"(a0), "r"(a1), "r"(a2), "r"(a3), "r"(b0), "r"(b1));
}

__device__ __forceinline__ uint32_t bsplit_hi(float x, float& rem) {
    __nv_bfloat16 hb = __float2bfloat16_rn(x);
    rem = x - __bfloat162float(hb);
    return (uint32_t)__bfloat16_as_ushort(hb);
}

__global__ __launch_bounds__(256) void k_gemm_mma(const float* __restrict__ A_in,
                                                  const float* __restrict__ W) {
    const float* A = A_in ? A_in : (const float*)g_h;
    extern __shared__ char sm[];
    int tid  = threadIdx.x;
    int wid  = tid >> 5;
    int lane = tid & 31;
    int r0   = blockIdx.x * 128;

    // ---- load A: fp32 -> bf16 hi/lo, row-major [128][128] padded ----
    {
        int r  = tid >> 1;
        int c0 = (tid & 1) * 64;
        bool valid = (r0 + r) < NN;
        const float4* src = (const float4*)(A + (size_t)(r0 + r) * DH + c0);
        char* dh = sm + SM_AH + r * ROWB + c0 * 2;
        char* dl = sm + SM_AL + r * ROWB + c0 * 2;
        #pragma unroll
        for (int i = 0; i < 16; i++) {
            float4 v = valid ? src[i] : make_float4(0.f, 0.f, 0.f, 0.f);
            float rx, ry, rz, rw;
            uint32_t hx = bsplit_hi(v.x, rx), hy = bsplit_hi(v.y, ry);
            uint32_t hz = bsplit_hi(v.z, rz), hw = bsplit_hi(v.w, rw);
            uint32_t h01 = hx | (hy << 16);
            uint32_t h23 = hz | (hw << 16);
            float d0, d1, d2, d3;
            uint32_t lx = bsplit_hi(rx, d0), ly = bsplit_hi(ry, d1);
            uint32_t lz = bsplit_hi(rz, d2), lw = bsplit_hi(rw, d3);
            uint32_t l01 = lx | (ly << 16);
            uint32_t l23 = lz | (lw << 16);
            *(uint2*)(dh + i * 8) = make_uint2(h01, h23);
            *(uint2*)(dl + i * 8) = make_uint2(l01, l23);
        }
    }
    // ---- load B: W[k][n] fp32 -> transpose + bf16 hi/lo split inline ----
    {
        int n  = tid >> 1;
        int c0 = (tid & 1) * 64;
        char* dh = sm + SM_BH + n * ROWB + c0 * 2;
        char* dl = sm + SM_BL + n * ROWB + c0 * 2;
        #pragma unroll
        for (int i = 0; i < 64; i += 2) {
            float v0 = W[(size_t)(c0 + i) * DH + n];
            float v1 = W[(size_t)(c0 + i + 1) * DH + n];
            float r0f, r1f, z;
            uint32_t h0 = bsplit_hi(v0, r0f), h1 = bsplit_hi(v1, r1f);
            uint32_t l0 = bsplit_hi(r0f, z),  l1 = bsplit_hi(r1f, z);
            *(uint32_t*)(dh + i * 2) = h0 | (h1 << 16);
            *(uint32_t*)(dl + i * 2) = l0 | (l1 << 16);
        }
    }
    __syncthreads();

    // warp grid: wm = wid & 1 (2 x 64 rows), wn = wid >> 1 (4 x 32 cols)
    int wm = (wid & 1) * 64;
    int wn = (wid >> 1) * 32;
    int g  = lane >> 2;      // 0..7
    int t  = lane & 3;       // 0..3

    float acc[4][4][4];      // [mt][nt][4]
    #pragma unroll
    for (int mt = 0; mt < 4; mt++)
        #pragma unroll
        for (int nt = 0; nt < 4; nt++)
            #pragma unroll
            for (int q = 0; q < 4; q++) acc[mt][nt][q] = 0.0f;

    #pragma unroll
    for (int ks = 0; ks < 8; ks++) {
        int kb = ks * 32;    // byte offset of k-chunk (16 elems * 2B)
        uint32_t bh[4][2], bl[4][2];
        #pragma unroll
        for (int nt = 0; nt < 4; nt++) {
            int nrow = wn + nt * 8 + g;
            const char* ph = sm + SM_BH + nrow * ROWB + kb + t * 4;
            const char* pl = sm + SM_BL + nrow * ROWB + kb + t * 4;
            bh[nt][0] = *(const uint32_t*)(ph);
            bh[nt][1] = *(const uint32_t*)(ph + 16);
            bl[nt][0] = *(const uint32_t*)(pl);
            bl[nt][1] = *(const uint32_t*)(pl + 16);
        }
        #pragma unroll
        for (int mt = 0; mt < 4; mt++) {
            int mrow = wm + mt * 16 + g;
            const char* ph = sm + SM_AH + mrow * ROWB + kb + t * 4;
            const char* pl = sm + SM_AL + mrow * ROWB + kb + t * 4;
            uint32_t ah0 = *(const uint32_t*)(ph);
            uint32_t ah1 = *(const uint32_t*)(ph + 8 * ROWB);
            uint32_t ah2 = *(const uint32_t*)(ph + 16);
            uint32_t ah3 = *(const uint32_t*)(ph + 8 * ROWB + 16);
            uint32_t al0 = *(const uint32_t*)(pl);
            uint32_t al1 = *(const uint32_t*)(pl + 8 * ROWB);
            uint32_t al2 = *(const uint32_t*)(pl + 16);
            uint32_t al3 = *(const uint32_t*)(pl + 8 * ROWB + 16);
            #pragma unroll
            for (int nt = 0; nt < 4; nt++) {
                mma_bf16(acc[mt][nt], ah0, ah1, ah2, ah3, bh[nt][0], bh[nt][1]);
                mma_bf16(acc[mt][nt], ah0, ah1, ah2, ah3, bl[nt][0], bl[nt][1]);
                mma_bf16(acc[mt][nt], al0, al1, al2, al3, bh[nt][0], bh[nt][1]);
            }
        }
    }

    // ---- epilogue: write D as fp16 to g_xwh ----
    #pragma unroll
    for (int mt = 0; mt < 4; mt++) {
        int row = r0 + wm + mt * 16 + g;
        #pragma unroll
        for (int nt = 0; nt < 4; nt++) {
            int col = wn + nt * 8 + t * 2;
            if (row < NN) {
                __half2 p = __floats2half2_rn(acc[mt][nt][0], acc[mt][nt][1]);
                *(uint32_t*)((char*)g_xwh + ((size_t)row * DH + col) * 2) =
                    *(uint32_t*)&p;
            }
            if (row + 8 < NN) {
                __half2 p = __floats2half2_rn(acc[mt][nt][2], acc[mt][nt][3]);
                *(uint32_t*)((char*)g_xwh + ((size_t)(row + 8) * DH + col) * 2) =
                    *(uint32_t*)&p;
            }
        }
    }
}

// ---------------- aggregation: g_h = relu( Ahat @ xw + b ) --------------
// one warp per node; lane handles 4 cols (4 halves = 8B per gather row).
// last layer: fuse FC head (dot with Wfc, + bfc) directly to out.
__global__ __launch_bounds__(256) void k_agg(const float* __restrict__ b,
                                             const float* __restrict__ Wfc,
                                             const float* __restrict__ bfc,
                                             float* __restrict__ out) {
    int warp = (blockIdx.x * blockDim.x + threadIdx.x) >> 5;
    int lane = threadIdx.x & 31;
    if (warp >= NN) return;
    int node = warp;

    const uint2* xw = (const uint2*)g_xwh;   // 4 halves per uint2

    float dv   = g_dinv[node];
    float self = dv * dv;

    uint2 sraw = xw[node * 32 + lane];
    __half2 s01 = *(__half2*)&sraw.x;
    __half2 s23 = *(__half2*)&sraw.y;
    float2 f01 = __half22float2(s01);
    float2 f23 = __half22float2(s23);
    float4 acc = make_float4(f01.x * self, f01.y * self,
                             f23.x * self, f23.y * self);

    int start = g_off[node];
    int m     = g_cnt[node];

    int j = 0;
    for (; j + 1 < m; j += 2) {
        int   s0 = g_ssrc[start + j];
        int   s1 = g_ssrc[start + j + 1];
        float n0 = g_snorm[start + j];
        float n1 = g_snorm[start + j + 1];
        uint2 r0 = xw[s0 * 32 + lane];
        uint2 r1 = xw[s1 * 32 + lane];
        float2 a01 = __half22float2(*(__half2*)&r0.x);
        float2 a23 = __half22float2(*(__half2*)&r0.y);
        float2 b01 = __half22float2(*(__half2*)&r1.x);
        float2 b23 = __half22float2(*(__half2*)&r1.y);
        acc.x += a01.x * n0 + b01.x * n1;
        acc.y += a01.y * n0 + b01.y * n1;
        acc.z += a23.x * n0 + b23.x * n1;
        acc.w += a23.y * n0 + b23.y * n1;
    }
    if (j < m) {
        int   s0 = g_ssrc[start + j];
        float n0 = g_snorm[start + j];
        uint2 r0 = xw[s0 * 32 + lane];
        float2 a01 = __half22float2(*(__half2*)&r0.x);
        float2 a23 = __half22float2(*(__half2*)&r0.y);
        acc.x += a01.x * n0;
        acc.y += a01.y * n0;
        acc.z += a23.x * n0;
        acc.w += a23.y * n0;
    }

    float4 bb = ((const float4*)b)[lane];
    acc.x = fmaxf(acc.x + bb.x, 0.0f);
    acc.y = fmaxf(acc.y + bb.y, 0.0f);
    acc.z = fmaxf(acc.z + bb.z, 0.0f);
    acc.w = fmaxf(acc.w + bb.w, 0.0f);

    if (Wfc) {
        float4 w = ((const float4*)Wfc)[lane];
        float sum = acc.x * w.x + acc.y * w.y + acc.z * w.z + acc.w * w.w;
        #pragma unroll
        for (int d = 16; d > 0; d >>= 1)
            sum += __shfl_xor_sync(0xFFFFFFFFu, sum, d);
        if (lane == 0) out[node] = sum + bfc[0];
    } else {
        ((float4*)g_h)[node * 32 + lane] = acc;
    }
}

// ---------------- launch -------------------------------------------------
extern "C" void kernel_launch(void* const* d_in, const int* in_sizes, int n_in,
                              void* d_out, int out_size) {
    const float* x    = (const float*)d_in[0];
    const void*  ei   = d_in[1];
    const float* W1   = (const float*)d_in[2];
    const float* b1   = (const float*)d_in[3];
    const float* W2   = (const float*)d_in[4];
    const float* b2   = (const float*)d_in[5];
    const float* W3   = (const float*)d_in[6];
    const float* b3   = (const float*)d_in[7];
    const float* Wfc  = (const float*)d_in[8];
    const float* bfc  = (const float*)d_in[9];
    float* out = (float*)d_out;

    static int smem_set = 0;
    if (!smem_set) {
        cudaFuncSetAttribute(k_gemm_mma,
                             cudaFuncAttributeMaxDynamicSharedMemorySize,
                             SM_GEMM_TOTAL);
        smem_set = 1;
    }

    const int TB = 256;
    int ge = (EE + TB - 1) / TB;
    int gn = (NN + TB - 1) / TB;

    k_dz<<<gn, TB>>>(ei);                 // 1
    k_convert_count<<<ge, TB>>>(ei);      // 2
    k_scan<<<1, 1024>>>();                // 3 (scan + dinv)
    k_scatter<<<ge, TB>>>();              // 4

    int ggemm = (NN + 127) / 128;
    int gwarp = (NN * 32 + TB - 1) / TB;

    // layer 1
    k_gemm_mma<<<ggemm, 256, SM_GEMM_TOTAL>>>(x, W1);        // 5
    k_agg<<<gwarp, TB>>>(b1, nullptr, nullptr, nullptr);     // 6 <- profiled
    // layer 2
    k_gemm_mma<<<ggemm, 256, SM_GEMM_TOTAL>>>(nullptr, W2);  // 7
    k_agg<<<gwarp, TB>>>(b2, nullptr, nullptr, nullptr);     // 8
    // layer 3 + fused FC head
    k_gemm_mma<<<ggemm, 256, SM_GEMM_TOTAL>>>(nullptr, W3);  // 9
    k_agg<<<gwarp, TB>>>(b3, Wfc, bfc, out);                 // 10
}